// round 3
// baseline (speedup 1.0000x reference)
#include <cuda_runtime.h>

// Problem constants
#define BATCH   16
#define NTOK    1024        // 32*32
#define HEADS   8
#define DIM     32
#define INP     384
#define OUP     384
#define INNER   256         // HEADS*DIM
#define QKVW    768         // 3*INNER
#define SCALE   0.17677669529663687f  // 32^-0.5

// Scratch (device globals: allocation-free per harness rules)
__device__ float g_qkv[(size_t)BATCH * NTOK * QKVW];        // ~50 MB
__device__ float g_att[(size_t)BATCH * NTOK * INNER];       // ~17 MB
__device__ float g_bias_t[(size_t)HEADS * NTOK * NTOK];     // 32 MB, [h][key][query]

// ---------------------------------------------------------------------------
// Packed fp32x2 helpers (SASS FFMA2 — only reachable via PTX fma.rn.f32x2)
// ---------------------------------------------------------------------------
typedef unsigned long long u64;

__device__ __forceinline__ u64 pack2(float lo, float hi) {
    u64 d;
    asm("mov.b64 %0, {%1, %2};" : "=l"(d)
        : "r"(__float_as_uint(lo)), "r"(__float_as_uint(hi)));
    return d;
}
__device__ __forceinline__ void unpack2(u64 v, float& lo, float& hi) {
    unsigned a, b;
    asm("mov.b64 {%0, %1}, %2;" : "=r"(a), "=r"(b) : "l"(v));
    lo = __uint_as_float(a); hi = __uint_as_float(b);
}
__device__ __forceinline__ u64 fma2(u64 a, u64 b, u64 c) {
    u64 d;
    asm("fma.rn.f32x2 %0, %1, %2, %3;" : "=l"(d) : "l"(a), "l"(b), "l"(c));
    return d;
}
__device__ __forceinline__ u64 mul2(u64 a, u64 b) {
    u64 d;
    asm("mul.rn.f32x2 %0, %1, %2;" : "=l"(d) : "l"(a), "l"(b));
    return d;
}

// ---------------------------------------------------------------------------
// Bias precompute: g_bias_t[h][m][n] = table[relidx[n][m] * HEADS + h]
// (n = query index, m = key index; n fastest => coalesced writes & reads).
// ---------------------------------------------------------------------------
__global__ __launch_bounds__(256)
void bias_kernel(const float* __restrict__ table, const int* __restrict__ relidx) {
    const int id = blockIdx.x * 256 + threadIdx.x;   // 0 .. 1024*1024-1
    const int m = id >> 10;
    const int n = id & 1023;
    const int idx = relidx[(size_t)n * NTOK + m];
    const float4 t0 = *(const float4*)&table[(size_t)idx * HEADS];
    const float4 t1 = *(const float4*)&table[(size_t)idx * HEADS + 4];
    const size_t base = (size_t)m * NTOK + n;
    g_bias_t[0 * (size_t)NTOK * NTOK + base] = t0.x;
    g_bias_t[1 * (size_t)NTOK * NTOK + base] = t0.y;
    g_bias_t[2 * (size_t)NTOK * NTOK + base] = t0.z;
    g_bias_t[3 * (size_t)NTOK * NTOK + base] = t0.w;
    g_bias_t[4 * (size_t)NTOK * NTOK + base] = t1.x;
    g_bias_t[5 * (size_t)NTOK * NTOK + base] = t1.y;
    g_bias_t[6 * (size_t)NTOK * NTOK + base] = t1.z;
    g_bias_t[7 * (size_t)NTOK * NTOK + base] = t1.w;
}

// ---------------------------------------------------------------------------
// Tiled fp32 GEMM with FFMA2 microtile + register-prefetch pipeline.
// C[M,N] = A[M,K] @ B[K,N] (+ bias). BM=BN=128, BK=8, 256 threads.
// Microtile 8x8 as 4 row-pairs x 8 cols: 32 FFMA2 + 8 packs per k-step.
// ---------------------------------------------------------------------------
template <bool ADD_BIAS>
__device__ __forceinline__ void gemm_body(const float* __restrict__ A,
                                          const float* __restrict__ Bm,
                                          const float* __restrict__ bias,
                                          float* __restrict__ C,
                                          int M, int N, int K) {
    __shared__ float As[8][132];   // [k][m], pitch 132 floats (16B-aligned rows)
    __shared__ float Bs[8][132];   // [k][n]

    const int tid = threadIdx.x;
    const int block_row = blockIdx.y * 128;
    const int block_col = blockIdx.x * 128;

    const int tx = tid & 15;            // 0..15
    const int ty = tid >> 4;            // 0..15
    const int r0 = ty * 4;              // rows r0..r0+3 and r0+64..r0+67
    const int c0 = tx * 4;              // cols c0..c0+3 and c0+64..c0+67

    const int a_row = tid >> 1;          // 0..127
    const int a_k4  = (tid & 1) * 4;     // 0 or 4
    const int b_k   = tid >> 5;          // 0..7
    const int b_c4  = (tid & 31) * 4;    // 0..124

    // acc2[p][j]: row-pair p (pairs: {r0,r0+1},{r0+2,r0+3},{r0+64,r0+65},{r0+66,r0+67})
    u64 acc2[4][8];
#pragma unroll
    for (int p = 0; p < 4; p++)
#pragma unroll
        for (int j = 0; j < 8; j++) acc2[p][j] = 0ull;

    // preload tile 0
    float4 av = *(const float4*)&A[(size_t)(block_row + a_row) * K + a_k4];
    float4 bv = *(const float4*)&Bm[(size_t)b_k * N + block_col + b_c4];

    for (int k0 = 0; k0 < K; k0 += 8) {
        As[a_k4 + 0][a_row] = av.x;
        As[a_k4 + 1][a_row] = av.y;
        As[a_k4 + 2][a_row] = av.z;
        As[a_k4 + 3][a_row] = av.w;
        *(float4*)&Bs[b_k][b_c4] = bv;
        __syncthreads();

        if (k0 + 8 < K) {  // prefetch next tile into registers (overlaps compute)
            av = *(const float4*)&A[(size_t)(block_row + a_row) * K + k0 + 8 + a_k4];
            bv = *(const float4*)&Bm[(size_t)(k0 + 8 + b_k) * N + block_col + b_c4];
        }

#pragma unroll
        for (int k = 0; k < 8; k++) {
            // A row-pairs (consecutive floats -> natural f32x2 pairs)
            const ulonglong2 aL = *(const ulonglong2*)&As[k][r0];
            const ulonglong2 aH = *(const ulonglong2*)&As[k][r0 + 64];
            u64 a2[4] = {aL.x, aL.y, aH.x, aH.y};
            // B scalars, broadcast-packed
            const float4 b0 = *(const float4*)&Bs[k][c0];
            const float4 b1 = *(const float4*)&Bs[k][c0 + 64];
            u64 bb[8];
            bb[0] = pack2(b0.x, b0.x); bb[1] = pack2(b0.y, b0.y);
            bb[2] = pack2(b0.z, b0.z); bb[3] = pack2(b0.w, b0.w);
            bb[4] = pack2(b1.x, b1.x); bb[5] = pack2(b1.y, b1.y);
            bb[6] = pack2(b1.z, b1.z); bb[7] = pack2(b1.w, b1.w);
#pragma unroll
            for (int p = 0; p < 4; p++)
#pragma unroll
                for (int j = 0; j < 8; j++)
                    acc2[p][j] = fma2(a2[p], bb[j], acc2[p][j]);
        }
        __syncthreads();
    }

    // unpack to acc[8][8] (i: 0..3 -> r0+i, 4..7 -> r0+64+(i-4))
    float acc[8][8];
#pragma unroll
    for (int p = 0; p < 4; p++) {
        const int iLo = (p < 2) ? (2 * p) : (4 + 2 * (p - 2));
#pragma unroll
        for (int j = 0; j < 8; j++)
            unpack2(acc2[p][j], acc[iLo][j], acc[iLo + 1][j]);
    }

#pragma unroll
    for (int ih = 0; ih < 2; ih++) {
#pragma unroll
        for (int i = 0; i < 4; i++) {
            const int row = block_row + r0 + ih * 64 + i;
#pragma unroll
            for (int jh = 0; jh < 2; jh++) {
                const int col = block_col + c0 + jh * 64;
                float4 v;
                v.x = acc[ih * 4 + i][jh * 4 + 0];
                v.y = acc[ih * 4 + i][jh * 4 + 1];
                v.z = acc[ih * 4 + i][jh * 4 + 2];
                v.w = acc[ih * 4 + i][jh * 4 + 3];
                if (ADD_BIAS) {
                    v.x += bias[col + 0];
                    v.y += bias[col + 1];
                    v.z += bias[col + 2];
                    v.w += bias[col + 3];
                }
                *(float4*)&C[(size_t)row * N + col] = v;
            }
        }
    }
}

__global__ __launch_bounds__(256)
void gemm_qkv_kernel(const float* __restrict__ x, const float* __restrict__ w) {
    gemm_body<false>(x, w, nullptr, g_qkv, BATCH * NTOK, QKVW, INP);
}

__global__ __launch_bounds__(256)
void gemm_out_kernel(const float* __restrict__ w, const float* __restrict__ bias,
                     float* __restrict__ out) {
    gemm_body<true>(g_att, w, bias, out, BATCH * NTOK, OUP, INNER);
}

// ---------------------------------------------------------------------------
// Flash attention, FFMA2 inner loops, precomputed transposed bias.
// Grid: (NTOK/128, HEADS, BATCH); block 128 threads; 1 thread = 1 q row.
// K/V staged 32 rows/tile in smem (register-prefetched); 32 cols per pass.
// ---------------------------------------------------------------------------
__global__ __launch_bounds__(128)
void attn_kernel(const float* __restrict__ qkv, float* __restrict__ att) {
    __shared__ float Ks[32][36];   // pitch 36 floats = 144B (16B-aligned rows)
    __shared__ float Vs[32][36];

    const int h   = blockIdx.y;
    const int b   = blockIdx.z;
    const int row = blockIdx.x * 128 + threadIdx.x;

    // q row -> packed registers, pre-scaled
    u64 q2[16];
    {
        const float* qp = qkv + (size_t)(b * NTOK + row) * QKVW + h * DIM;
#pragma unroll
        for (int j = 0; j < 8; j++) {
            float4 v = *(const float4*)(qp + j * 4);
            q2[2 * j]     = pack2(v.x * SCALE, v.y * SCALE);
            q2[2 * j + 1] = pack2(v.z * SCALE, v.w * SCALE);
        }
    }

    u64 o2[16];
#pragma unroll
    for (int j = 0; j < 16; j++) o2[j] = 0ull;
    float m = -1e30f, l = 0.f;

    const float* bh = g_bias_t + (size_t)h * NTOK * NTOK + row;   // [key][query]

    // smem staging: thread t loads K/V row c = t/4, 8 floats at (t%4)*8
    const int lc = threadIdx.x >> 2;
    const int lx = (threadIdx.x & 3) * 8;
    const float* kbase = qkv + (size_t)(b * NTOK + lc) * QKVW + INNER + h * DIM + lx;

    // prefetch tile 0
    float4 pk0 = *(const float4*)kbase;
    float4 pk1 = *(const float4*)(kbase + 4);
    float4 pv0 = *(const float4*)(kbase + INNER);
    float4 pv1 = *(const float4*)(kbase + INNER + 4);

    for (int kb = 0; kb < NTOK; kb += 32) {
        *(float4*)&Ks[lc][lx]     = pk0;  *(float4*)&Ks[lc][lx + 4] = pk1;
        *(float4*)&Vs[lc][lx]     = pv0;  *(float4*)&Vs[lc][lx + 4] = pv1;
        __syncthreads();

        if (kb + 32 < NTOK) {  // prefetch next tile (overlaps compute)
            const float* kp = kbase + (size_t)(kb + 32) * QKVW;
            pk0 = *(const float4*)kp;            pk1 = *(const float4*)(kp + 4);
            pv0 = *(const float4*)(kp + INNER);  pv1 = *(const float4*)(kp + INNER + 4);
        }

        float s[32];
        // bias init (coalesced, L2-resident); LDG latency overlaps QK dots below
#pragma unroll
        for (int cc = 0; cc < 32; cc++)
            s[cc] = __ldg(bh + (size_t)(kb + cc) * NTOK);

        // scores: q . K[cc]  (smem reads are warp-broadcast)
#pragma unroll
        for (int cc = 0; cc < 32; cc++) {
            const ulonglong2* kr = (const ulonglong2*)&Ks[cc][0];
            u64 acc = 0ull;
#pragma unroll
            for (int jj = 0; jj < 4; jj++) {
                const ulonglong2 kp2 = kr[jj];
                acc = fma2(q2[2 * jj],     kp2.x, acc);
                acc = fma2(q2[2 * jj + 1], kp2.y, acc);
            }
            // second half of the 32-dim: pairs 8..15
            const ulonglong2* kr2 = (const ulonglong2*)&Ks[cc][16];
#pragma unroll
            for (int jj = 0; jj < 4; jj++) {
                const ulonglong2 kp2 = kr2[jj];
                acc = fma2(q2[8 + 2 * jj],     kp2.x, acc);
                acc = fma2(q2[8 + 2 * jj + 1], kp2.y, acc);
            }
            float alo, ahi;
            unpack2(acc, alo, ahi);
            s[cc] += alo + ahi;
        }

        // online softmax update over 32 cols
        float tmax = s[0];
#pragma unroll
        for (int cc = 1; cc < 32; cc++) tmax = fmaxf(tmax, s[cc]);
        const float mn   = fmaxf(m, tmax);
        const float corr = __expf(m - mn);
        float ps = 0.f;
#pragma unroll
        for (int cc = 0; cc < 32; cc++) {
            s[cc] = __expf(s[cc] - mn);
            ps += s[cc];
        }
        l = l * corr + ps;
        const u64 corr2 = pack2(corr, corr);
#pragma unroll
        for (int j = 0; j < 16; j++) o2[j] = mul2(o2[j], corr2);

        // o += p * V[cc]
#pragma unroll
        for (int cc = 0; cc < 32; cc++) {
            const u64 pp = pack2(s[cc], s[cc]);
            const ulonglong2* vr = (const ulonglong2*)&Vs[cc][0];
#pragma unroll
            for (int jj = 0; jj < 4; jj++) {
                const ulonglong2 vp2 = vr[jj];
                o2[2 * jj]     = fma2(pp, vp2.x, o2[2 * jj]);
                o2[2 * jj + 1] = fma2(pp, vp2.y, o2[2 * jj + 1]);
            }
            const ulonglong2* vr2 = (const ulonglong2*)&Vs[cc][16];
#pragma unroll
            for (int jj = 0; jj < 4; jj++) {
                const ulonglong2 vp2 = vr2[jj];
                o2[8 + 2 * jj]     = fma2(pp, vp2.x, o2[8 + 2 * jj]);
                o2[8 + 2 * jj + 1] = fma2(pp, vp2.y, o2[8 + 2 * jj + 1]);
            }
        }
        m = mn;
        __syncthreads();
    }

    const float inv = 1.f / l;
    float* op = att + (size_t)(b * NTOK + row) * INNER + h * DIM;
#pragma unroll
    for (int j = 0; j < 8; j++) {
        float a, bb, c, d;
        unpack2(o2[2 * j], a, bb);
        unpack2(o2[2 * j + 1], c, d);
        float4 v;
        v.x = a * inv; v.y = bb * inv; v.z = c * inv; v.w = d * inv;
        *(float4*)(op + j * 4) = v;
    }
}

// ---------------------------------------------------------------------------
extern "C" void kernel_launch(void* const* d_in, const int* in_sizes, int n_in,
                              void* d_out, int out_size) {
    const float* x      = (const float*)d_in[0];
    const float* w_qkv  = (const float*)d_in[1];
    const float* table  = (const float*)d_in[2];
    const float* w_out  = (const float*)d_in[3];
    const float* b_out  = (const float*)d_in[4];
    const int*   relidx = (const int*)d_in[5];
    float*       out    = (float*)d_out;

    float* qkv_ptr = nullptr;
    float* att_ptr = nullptr;
    cudaGetSymbolAddress((void**)&qkv_ptr, g_qkv);
    cudaGetSymbolAddress((void**)&att_ptr, g_att);

    // 0) Precompute transposed bias: [h][key][query]
    bias_kernel<<<(NTOK * NTOK) / 256, 256>>>(table, relidx);

    // 1) QKV projection: [16384,384] @ [384,768] -> g_qkv
    {
        dim3 grid(QKVW / 128, (BATCH * NTOK) / 128);
        gemm_qkv_kernel<<<grid, 256>>>(x, w_qkv);
    }
    // 2) Flash attention with relative bias -> g_att
    {
        dim3 grid(NTOK / 128, HEADS, BATCH);
        attn_kernel<<<grid, 128>>>(qkv_ptr, att_ptr);
    }
    // 3) Output projection: [16384,256] @ [256,384] + b_out -> d_out
    {
        dim3 grid(OUP / 128, (BATCH * NTOK) / 128);
        gemm_out_kernel<<<grid, 256>>>(w_out, b_out, out);
    }
}

// round 12
// speedup vs baseline: 1.4874x; 1.4874x over previous
#include <cuda_runtime.h>
#include <cuda_fp16.h>
#include <cstdint>

// Problem constants
#define BATCH   16
#define NTOK    1024        // 32*32
#define HEADS   8
#define DIM     32
#define INP     384
#define OUP     384
#define INNER   256         // HEADS*DIM
#define QKVW    768         // 3*INNER
#define SCALE   0.17677669529663687f  // 32^-0.5

// Scratch (device globals: allocation-free per harness rules)
__device__ float    g_qkv[(size_t)BATCH * NTOK * QKVW];      // ~50 MB
__device__ float    g_att[(size_t)BATCH * NTOK * INNER];     // ~17 MB
// bias pair-packed: [h][key/2][query] as u32 = {lo: key even, hi: key odd} fp16
__device__ uint32_t g_bias2[(size_t)HEADS * (NTOK / 2) * NTOK];  // 16 MB

// ===========================================================================
// fp16 pack/split helpers
// ===========================================================================
__device__ __forceinline__ uint32_t h2_from(__half a, __half b) {
    __half2 t = __halves2half2(a, b);   // lo=a, hi=b
    return *(uint32_t*)&t;
}
__device__ __forceinline__ void split2(float a, float b, uint32_t& hi, uint32_t& lo) {
    __half ha = __float2half_rn(a), hb = __float2half_rn(b);
    hi = h2_from(ha, hb);
    __half ra = __float2half_rn(a - __half2float(ha));
    __half rb = __float2half_rn(b - __half2float(hb));
    lo = h2_from(ra, rb);
}
// mma.sync m16n8k16 fp16 -> fp32 (compiles to HMMA on sm_103)
__device__ __forceinline__ void mma16816(float c[4], const uint32_t a[4],
                                         uint32_t b0, uint32_t b1) {
    asm volatile(
        "mma.sync.aligned.m16n8k16.row.col.f32.f16.f16.f32 "
        "{%0,%1,%2,%3}, {%4,%5,%6,%7}, {%8,%9}, {%0,%1,%2,%3};"
        : "+f"(c[0]), "+f"(c[1]), "+f"(c[2]), "+f"(c[3])
        : "r"(a[0]), "r"(a[1]), "r"(a[2]), "r"(a[3]), "r"(b0), "r"(b1));
}
__device__ __forceinline__ float red_max4(float v) {
    v = fmaxf(v, __shfl_xor_sync(0xFFFFFFFFu, v, 1));
    v = fmaxf(v, __shfl_xor_sync(0xFFFFFFFFu, v, 2));
    return v;
}
__device__ __forceinline__ float red_sum4(float v) {
    v += __shfl_xor_sync(0xFFFFFFFFu, v, 1);
    v += __shfl_xor_sync(0xFFFFFFFFu, v, 2);
    return v;
}

// ===========================================================================
// Packed fp32x2 helpers for the projection GEMMs (SASS FFMA2)
// ===========================================================================
typedef unsigned long long u64;
__device__ __forceinline__ u64 pack2(float lo, float hi) {
    u64 d;
    asm("mov.b64 %0, {%1, %2};" : "=l"(d)
        : "r"(__float_as_uint(lo)), "r"(__float_as_uint(hi)));
    return d;
}
__device__ __forceinline__ void unpack2(u64 v, float& lo, float& hi) {
    unsigned a, b;
    asm("mov.b64 {%0, %1}, %2;" : "=r"(a), "=r"(b) : "l"(v));
    lo = __uint_as_float(a); hi = __uint_as_float(b);
}
__device__ __forceinline__ u64 fma2(u64 a, u64 b, u64 c) {
    u64 d;
    asm("fma.rn.f32x2 %0, %1, %2, %3;" : "=l"(d) : "l"(a), "l"(b), "l"(c));
    return d;
}

// ===========================================================================
// Bias precompute: g_bias2[h][m2][n] = {table[relidx[n][2m2]*8+h],
//                                       table[relidx[n][2m2+1]*8+h]} fp16x2
// n fastest -> coalesced u32 writes; relidx column reads scattered (one-time).
// ===========================================================================
__global__ __launch_bounds__(256)
void bias2_kernel(const float* __restrict__ table, const int* __restrict__ relidx) {
    const int id = blockIdx.x * 256 + threadIdx.x;   // 0 .. 512K-1
    const int m2 = id >> 10;          // key pair index (0..511)
    const int n  = id & 1023;         // query
    const int i0 = relidx[(size_t)n * NTOK + 2 * m2];
    const int i1 = relidx[(size_t)n * NTOK + 2 * m2 + 1];
    const float4 a0 = *(const float4*)&table[(size_t)i0 * HEADS];
    const float4 a1 = *(const float4*)&table[(size_t)i0 * HEADS + 4];
    const float4 b0 = *(const float4*)&table[(size_t)i1 * HEADS];
    const float4 b1 = *(const float4*)&table[(size_t)i1 * HEADS + 4];
    const float ea[8] = {a0.x, a0.y, a0.z, a0.w, a1.x, a1.y, a1.z, a1.w};
    const float eb[8] = {b0.x, b0.y, b0.z, b0.w, b1.x, b1.y, b1.z, b1.w};
#pragma unroll
    for (int h = 0; h < 8; h++)
        g_bias2[((size_t)h * 512 + m2) * NTOK + n] =
            h2_from(__float2half_rn(ea[h]), __float2half_rn(eb[h]));
}

// ===========================================================================
// Projection GEMMs (fp32 FFMA2, verified passing in round 3)
// ===========================================================================
template <bool ADD_BIAS>
__device__ __forceinline__ void gemm_body(const float* __restrict__ A,
                                          const float* __restrict__ Bm,
                                          const float* __restrict__ bias,
                                          float* __restrict__ C,
                                          int M, int N, int K) {
    __shared__ float As[8][132];
    __shared__ float Bs[8][132];

    const int tid = threadIdx.x;
    const int block_row = blockIdx.y * 128;
    const int block_col = blockIdx.x * 128;

    const int tx = tid & 15;
    const int ty = tid >> 4;
    const int r0 = ty * 4;
    const int c0 = tx * 4;

    const int a_row = tid >> 1;
    const int a_k4  = (tid & 1) * 4;
    const int b_k   = tid >> 5;
    const int b_c4  = (tid & 31) * 4;

    u64 acc2[4][8];
#pragma unroll
    for (int p = 0; p < 4; p++)
#pragma unroll
        for (int j = 0; j < 8; j++) acc2[p][j] = 0ull;

    float4 av = *(const float4*)&A[(size_t)(block_row + a_row) * K + a_k4];
    float4 bv = *(const float4*)&Bm[(size_t)b_k * N + block_col + b_c4];

    for (int k0 = 0; k0 < K; k0 += 8) {
        As[a_k4 + 0][a_row] = av.x;
        As[a_k4 + 1][a_row] = av.y;
        As[a_k4 + 2][a_row] = av.z;
        As[a_k4 + 3][a_row] = av.w;
        *(float4*)&Bs[b_k][b_c4] = bv;
        __syncthreads();

        if (k0 + 8 < K) {
            av = *(const float4*)&A[(size_t)(block_row + a_row) * K + k0 + 8 + a_k4];
            bv = *(const float4*)&Bm[(size_t)(k0 + 8 + b_k) * N + block_col + b_c4];
        }

#pragma unroll
        for (int k = 0; k < 8; k++) {
            const ulonglong2 aL = *(const ulonglong2*)&As[k][r0];
            const ulonglong2 aH = *(const ulonglong2*)&As[k][r0 + 64];
            u64 a2[4] = {aL.x, aL.y, aH.x, aH.y};
            const float4 b0 = *(const float4*)&Bs[k][c0];
            const float4 b1 = *(const float4*)&Bs[k][c0 + 64];
            u64 bb[8];
            bb[0] = pack2(b0.x, b0.x); bb[1] = pack2(b0.y, b0.y);
            bb[2] = pack2(b0.z, b0.z); bb[3] = pack2(b0.w, b0.w);
            bb[4] = pack2(b1.x, b1.x); bb[5] = pack2(b1.y, b1.y);
            bb[6] = pack2(b1.z, b1.z); bb[7] = pack2(b1.w, b1.w);
#pragma unroll
            for (int p = 0; p < 4; p++)
#pragma unroll
                for (int j = 0; j < 8; j++)
                    acc2[p][j] = fma2(a2[p], bb[j], acc2[p][j]);
        }
        __syncthreads();
    }

    float acc[8][8];
#pragma unroll
    for (int p = 0; p < 4; p++) {
        const int iLo = (p < 2) ? (2 * p) : (4 + 2 * (p - 2));
#pragma unroll
        for (int j = 0; j < 8; j++)
            unpack2(acc2[p][j], acc[iLo][j], acc[iLo + 1][j]);
    }

#pragma unroll
    for (int ih = 0; ih < 2; ih++) {
#pragma unroll
        for (int i = 0; i < 4; i++) {
            const int row = block_row + r0 + ih * 64 + i;
#pragma unroll
            for (int jh = 0; jh < 2; jh++) {
                const int col = block_col + c0 + jh * 64;
                float4 v;
                v.x = acc[ih * 4 + i][jh * 4 + 0];
                v.y = acc[ih * 4 + i][jh * 4 + 1];
                v.z = acc[ih * 4 + i][jh * 4 + 2];
                v.w = acc[ih * 4 + i][jh * 4 + 3];
                if (ADD_BIAS) {
                    v.x += bias[col + 0]; v.y += bias[col + 1];
                    v.z += bias[col + 2]; v.w += bias[col + 3];
                }
                *(float4*)&C[(size_t)row * N + col] = v;
            }
        }
    }
}

__global__ __launch_bounds__(256)
void gemm_qkv_kernel(const float* __restrict__ x, const float* __restrict__ w) {
    gemm_body<false>(x, w, nullptr, g_qkv, BATCH * NTOK, QKVW, INP);
}
__global__ __launch_bounds__(256)
void gemm_out_kernel(const float* __restrict__ w, const float* __restrict__ bias,
                     float* __restrict__ out) {
    gemm_body<true>(g_att, w, bias, out, BATCH * NTOK, OUP, INNER);
}

// ===========================================================================
// FlashAttention-2 with mma.sync m16n8k16 (HMMA fallback on sm_103).
// Grid (8 q-blocks, 8 heads, 16 batch); 128 threads; warp = 32 q-rows.
// 3-term fp16 hi/lo splits on both QK^T and PV keep error ~1e-5.
// ===========================================================================
#define QPITCH 40   // halves per Q/K smem row (80B; conflict-free frag loads)
#define VPITCH 72   // halves per V^T smem row (144B; conflict-free frag loads)

__global__ __launch_bounds__(128)
void attn_kernel(float* __restrict__ att) {
    __shared__ __align__(16) __half Qh[128 * QPITCH], Ql[128 * QPITCH];
    __shared__ __align__(16) __half Kh[64 * QPITCH],  Kl[64 * QPITCH];
    __shared__ __align__(16) __half Vh[32 * VPITCH],  Vl[32 * VPITCH];

    const int tid  = threadIdx.x;
    const int wid  = tid >> 5;
    const int lane = tid & 31;
    const int gid  = lane >> 2;    // group id (row within tile)
    const int tig  = lane & 3;     // thread in group (col pair)
    const int h  = blockIdx.y;
    const int b  = blockIdx.z;
    const int q0 = blockIdx.x * 128;

    // ---- stage Q (scaled, fp16 hi/lo split) ----
    {
        const float* qp = g_qkv + ((size_t)(b * NTOK + q0 + tid)) * QKVW + h * DIM;
        uint32_t* qh32 = (uint32_t*)(Qh + tid * QPITCH);
        uint32_t* ql32 = (uint32_t*)(Ql + tid * QPITCH);
#pragma unroll
        for (int j = 0; j < 16; j++) {
            float2 v = *(const float2*)(qp + 2 * j);
            split2(v.x * SCALE, v.y * SCALE, qh32[j], ql32[j]);
        }
    }
    __syncthreads();

    // ---- Q fragments (m16n8k16 A layout; contiguous f16 pairs) ----
    uint32_t qa_h[2][2][4], qa_l[2][2][4];
#pragma unroll
    for (int mt = 0; mt < 2; mt++) {
        const int r = wid * 32 + mt * 16 + gid;
#pragma unroll
        for (int ks = 0; ks < 2; ks++) {
            const int c0 = 16 * ks + 2 * tig;
            qa_h[mt][ks][0] = *(const uint32_t*)(Qh + r * QPITCH + c0);
            qa_h[mt][ks][1] = *(const uint32_t*)(Qh + (r + 8) * QPITCH + c0);
            qa_h[mt][ks][2] = *(const uint32_t*)(Qh + r * QPITCH + c0 + 8);
            qa_h[mt][ks][3] = *(const uint32_t*)(Qh + (r + 8) * QPITCH + c0 + 8);
            qa_l[mt][ks][0] = *(const uint32_t*)(Ql + r * QPITCH + c0);
            qa_l[mt][ks][1] = *(const uint32_t*)(Ql + (r + 8) * QPITCH + c0);
            qa_l[mt][ks][2] = *(const uint32_t*)(Ql + r * QPITCH + c0 + 8);
            qa_l[mt][ks][3] = *(const uint32_t*)(Ql + (r + 8) * QPITCH + c0 + 8);
        }
    }

    // row slots per lane: rs = mt*2 + rh; rows (wid*32 + mt*16 + gid) and (+8)
    float m_[4] = {-1e30f, -1e30f, -1e30f, -1e30f};
    float l_[4] = {0.f, 0.f, 0.f, 0.f};
    float od[2][4][4];
#pragma unroll
    for (int mt = 0; mt < 2; mt++)
#pragma unroll
        for (int dt = 0; dt < 4; dt++)
#pragma unroll
            for (int e = 0; e < 4; e++) od[mt][dt][e] = 0.f;

    const uint32_t* bb = g_bias2 + (size_t)h * 512 * NTOK;

    for (int kb = 0; kb < NTOK; kb += 64) {
        // ---- stage K (hi/lo) + V^T (hi/lo): 2 threads per key ----
        __syncthreads();
        {
            const int lk = tid >> 1;
            const int hd = (tid & 1) * 16;
            const float* kp = g_qkv + ((size_t)(b * NTOK + kb + lk)) * QKVW + INNER + h * DIM + hd;
            const float* vp = kp + INNER;
            uint32_t* kh32 = (uint32_t*)(Kh + lk * QPITCH + hd);
            uint32_t* kl32 = (uint32_t*)(Kl + lk * QPITCH + hd);
#pragma unroll
            for (int j = 0; j < 8; j++) {
                float2 v = *(const float2*)(kp + 2 * j);
                split2(v.x, v.y, kh32[j], kl32[j]);
            }
#pragma unroll
            for (int j = 0; j < 16; j++) {
                const float v = vp[j];
                const __half hv = __float2half_rn(v);
                Vh[(hd + j) * VPITCH + lk] = hv;
                Vl[(hd + j) * VPITCH + lk] = __float2half_rn(v - __half2float(hv));
            }
        }
        __syncthreads();

        // ---- S = Q K^T (3-term) ----
        float sc[2][8][4];
#pragma unroll
        for (int mt = 0; mt < 2; mt++)
#pragma unroll
            for (int nt = 0; nt < 8; nt++)
#pragma unroll
                for (int e = 0; e < 4; e++) sc[mt][nt][e] = 0.f;

#pragma unroll
        for (int nt = 0; nt < 8; nt++) {
            const int krow = nt * 8 + gid;
#pragma unroll
            for (int ks = 0; ks < 2; ks++) {
                const int c0 = 16 * ks + 2 * tig;
                const uint32_t bh0 = *(const uint32_t*)(Kh + krow * QPITCH + c0);
                const uint32_t bh1 = *(const uint32_t*)(Kh + krow * QPITCH + c0 + 8);
                const uint32_t bl0 = *(const uint32_t*)(Kl + krow * QPITCH + c0);
                const uint32_t bl1 = *(const uint32_t*)(Kl + krow * QPITCH + c0 + 8);
#pragma unroll
                for (int mt = 0; mt < 2; mt++) {
                    mma16816(sc[mt][nt], qa_h[mt][ks], bh0, bh1);
                    mma16816(sc[mt][nt], qa_l[mt][ks], bh0, bh1);
                    mma16816(sc[mt][nt], qa_h[mt][ks], bl0, bl1);
                }
            }
        }

        // ---- bias add (pair-packed u32 gathers, L2-resident) ----
#pragma unroll
        for (int mt = 0; mt < 2; mt++) {
            const int qr = q0 + wid * 32 + mt * 16 + gid;
#pragma unroll
            for (int nt = 0; nt < 8; nt++) {
                const size_t m2 = (size_t)(kb / 2 + nt * 4 + tig);
                const uint32_t v0 = __ldg(bb + m2 * NTOK + qr);
                const uint32_t v1 = __ldg(bb + m2 * NTOK + qr + 8);
                const __half2 h0 = *(const __half2*)&v0;
                const __half2 h1 = *(const __half2*)&v1;
                sc[mt][nt][0] += __low2float(h0);
                sc[mt][nt][1] += __high2float(h0);
                sc[mt][nt][2] += __low2float(h1);
                sc[mt][nt][3] += __high2float(h1);
            }
        }

        // ---- online softmax (rows owned by quads; bfly over tig) ----
        float corr[4];
#pragma unroll
        for (int mt = 0; mt < 2; mt++) {
#pragma unroll
            for (int rh = 0; rh < 2; rh++) {
                const int rs = mt * 2 + rh;
                float mx = -1e30f;
#pragma unroll
                for (int nt = 0; nt < 8; nt++) {
                    mx = fmaxf(mx, sc[mt][nt][rh * 2]);
                    mx = fmaxf(mx, sc[mt][nt][rh * 2 + 1]);
                }
                mx = red_max4(mx);
                const float mn = fmaxf(m_[rs], mx);
                corr[rs] = __expf(m_[rs] - mn);
                m_[rs] = mn;
                float ps = 0.f;
#pragma unroll
                for (int nt = 0; nt < 8; nt++) {
                    const float e0 = __expf(sc[mt][nt][rh * 2] - mn);
                    const float e1 = __expf(sc[mt][nt][rh * 2 + 1] - mn);
                    sc[mt][nt][rh * 2] = e0;
                    sc[mt][nt][rh * 2 + 1] = e1;
                    ps += e0 + e1;
                }
                ps = red_sum4(ps);
                l_[rs] = l_[rs] * corr[rs] + ps;
#pragma unroll
                for (int dt = 0; dt < 4; dt++) {
                    od[mt][dt][rh * 2] *= corr[rs];
                    od[mt][dt][rh * 2 + 1] *= corr[rs];
                }
            }
        }

        // ---- O += P V (3-term); P frags built from S registers ----
#pragma unroll
        for (int ks = 0; ks < 4; ks++) {
            uint32_t pa_h[2][4], pa_l[2][4];
#pragma unroll
            for (int mt = 0; mt < 2; mt++) {
                split2(sc[mt][2 * ks][0], sc[mt][2 * ks][1], pa_h[mt][0], pa_l[mt][0]);
                split2(sc[mt][2 * ks][2], sc[mt][2 * ks][3], pa_h[mt][1], pa_l[mt][1]);
                split2(sc[mt][2 * ks + 1][0], sc[mt][2 * ks + 1][1], pa_h[mt][2], pa_l[mt][2]);
                split2(sc[mt][2 * ks + 1][2], sc[mt][2 * ks + 1][3], pa_h[mt][3], pa_l[mt][3]);
            }
#pragma unroll
            for (int dt = 0; dt < 4; dt++) {
                const int vrow = dt * 8 + gid;
                const int c0 = 16 * ks + 2 * tig;
                const uint32_t bh0 = *(const uint32_t*)(Vh + vrow * VPITCH + c0);
                const uint32_t bh1 = *(const uint32_t*)(Vh + vrow * VPITCH + c0 + 8);
                const uint32_t bl0 = *(const uint32_t*)(Vl + vrow * VPITCH + c0);
                const uint32_t bl1 = *(const uint32_t*)(Vl + vrow * VPITCH + c0 + 8);
#pragma unroll
                for (int mt = 0; mt < 2; mt++) {
                    mma16816(od[mt][dt], pa_h[mt], bh0, bh1);
                    mma16816(od[mt][dt], pa_l[mt], bh0, bh1);
                    mma16816(od[mt][dt], pa_h[mt], bl0, bl1);
                }
            }
        }
    }

    // ---- epilogue: O /= l, write g_att ----
#pragma unroll
    for (int mt = 0; mt < 2; mt++) {
        const int r = q0 + wid * 32 + mt * 16 + gid;
        const float inv0 = 1.f / l_[mt * 2 + 0];
        const float inv1 = 1.f / l_[mt * 2 + 1];
        float* op0 = att + ((size_t)(b * NTOK + r)) * INNER + h * DIM;
        float* op1 = att + ((size_t)(b * NTOK + r + 8)) * INNER + h * DIM;
#pragma unroll
        for (int dt = 0; dt < 4; dt++) {
            const int d = dt * 8 + 2 * tig;
            float2 v0; v0.x = od[mt][dt][0] * inv0; v0.y = od[mt][dt][1] * inv0;
            float2 v1; v1.x = od[mt][dt][2] * inv1; v1.y = od[mt][dt][3] * inv1;
            *(float2*)(op0 + d) = v0;
            *(float2*)(op1 + d) = v1;
        }
    }
}

// ===========================================================================
extern "C" void kernel_launch(void* const* d_in, const int* in_sizes, int n_in,
                              void* d_out, int out_size) {
    const float* x      = (const float*)d_in[0];
    const float* w_qkv  = (const float*)d_in[1];
    const float* table  = (const float*)d_in[2];
    const float* w_out  = (const float*)d_in[3];
    const float* b_out  = (const float*)d_in[4];
    const int*   relidx = (const int*)d_in[5];
    float*       out    = (float*)d_out;

    float* att_ptr = nullptr;
    cudaGetSymbolAddress((void**)&att_ptr, g_att);

    // 0) Precompute pair-packed fp16 bias: [h][key/2][query]
    bias2_kernel<<<(512 * NTOK) / 256, 256>>>(table, relidx);

    // 1) QKV projection (fp32 FFMA2)
    {
        dim3 grid(QKVW / 128, (BATCH * NTOK) / 128);
        gemm_qkv_kernel<<<grid, 256>>>(x, w_qkv);
    }
    // 2) FlashAttention-2 via mma.sync fp16 3-term split
    {
        dim3 grid(NTOK / 128, HEADS, BATCH);
        attn_kernel<<<grid, 128>>>(att_ptr);
    }
    // 3) Output projection (fp32 FFMA2)
    {
        dim3 grid(OUP / 128, (BATCH * NTOK) / 128);
        gemm_out_kernel<<<grid, 256>>>(w_out, b_out, out);
    }
}